// round 5
// baseline (speedup 1.0000x reference)
#include <cuda_runtime.h>

// NaturalCubicSplinePotential — GB300 sm_103a
//
// R4: single fused kernel. Reduce folded in via last-block ticket pattern
// (deterministic: final block sums the 1024 partials in fixed index order).
// Bucketize switched to magic-number floor (2^23) with MIDPOINT-recentered
// table coefficients: v = u - 0.5 in [-0.5, 0.5); half-integer ties are safe
// because the spline is C2-continuous (adjacent pieces agree at knots).
//
// Table: [1,4,1] tridiagonal inverse in closed form (lam = 2+sqrt(3)),
// truncated 31-tap convolution (error ~2e-10), padded to 256 intervals so the
// hot loop needs NO clamping (pad entries = recentered boundary extrapolation).

#define NM 8
#define NN 128
#define TABN 256          // padded table entries per marginal
#define PADL 64           // pad below interval 0
#define EVAL_BLOCKS 1024
#define F4_PER_BLOCK 4096 // 16384 elements per block
#define NTHREADS 256
#define CONV_R 15         // truncation radius of inverse-matrix convolution

__device__ float g_part[EVAL_BLOCKS];
__device__ unsigned int g_ticket;   // zero-initialized; self-resets each call

// lam = 2+sqrt(3); log2(lam) = 1.89996863
#define LOG2_LAM 1.89996863f
#define INV_D0   1.07735027f   // 1/(1-lam^-2)
#define MAGIC    12582912.0f   // 1.5 * 2^23
#define MAGIC_I  0x4B400000

// ---------------------------------------------------------------------------
__device__ __forceinline__ void eval_lane(float xv, const float4* __restrict__ tab,
                                          float& acc)
{
    // t5 = (x+4)*127/8 + 64 - 0.5  (pads folded: 4*15.875 + 63.5 = 127.0)
    const float t5 = __fmaf_rn(xv, 15.875f, 127.0f);
    const float tm = t5 + MAGIC;                    // round(t5) = floor(t) a.e.
    const int   i  = __float_as_int(tm) - MAGIC_I;  // integer interval index
    const float v  = t5 - (tm - MAGIC);             // v = u - 0.5 in [-0.5,0.5)
    const float4 cf = tab[i];
    acc += __fmaf_rn(v, __fmaf_rn(v, __fmaf_rn(v, cf.w, cf.z), cf.y), cf.x);
}

__global__ void __launch_bounds__(NTHREADS) eval_kernel(const float4* __restrict__ x4,
                                                        const float* __restrict__ nodal,
                                                        float* __restrict__ out)
{
    __shared__ float4 tab[TABN];
    __shared__ float  ysh[NN];
    __shared__ float  pw[256];                          // pw[k] = lam^{-k}
    __shared__ float  srsh[NN + 2 * (CONV_R + 1)];      // padded (-1)^j * r_j
    __shared__ float  csh[NN];
    __shared__ float  wsum[NTHREADS / 32];
    __shared__ bool   amLast;

    const int tid = threadIdx.x;
    // slab (bs,f) = 65536 elems = 4 blocks; marginal index = slab & 7
    const int m = (blockIdx.x >> 2) & 7;

    // ---- prologue: closed-form spline solve + recentered padded table -------
    if (tid < NN)
        ysh[tid] = nodal[m * NN + tid];
    pw[tid] = exp2f(-LOG2_LAM * (float)tid);
    if (tid < NN + 2 * (CONV_R + 1))
        srsh[tid] = 0.0f;
    __syncthreads();

    const float inv_h2 = (127.0f / 8.0f) * (127.0f / 8.0f);
    if (tid >= 1 && tid <= 126) {
        float r = 3.0f * (ysh[tid - 1] - 2.0f * ysh[tid] + ysh[tid + 1]) * inv_h2;
        srsh[(CONV_R + 1) + tid] = (tid & 1) ? -r : r;
    }
    __syncthreads();

    if (tid < NN) {
        const int i = tid;
        float c = 0.0f;
        if (i >= 1 && i <= 126) {
#pragma unroll
            for (int dj = -CONV_R; dj <= CONV_R; ++dj) {
                const int j  = i + dj;
                const int jc = min(max(j, 1), 126);
                const int mi = min(i, jc);
                const int mx = max(i, jc);
                const float w = pw[(dj < 0 ? -dj : dj) + 1]
                              * (1.0f - pw[2 * mi])
                              * (1.0f - pw[2 * (127 - mx)]);
                c = __fmaf_rn(w, srsh[(CONV_R + 1) + j], c);
            }
            c *= INV_D0;
            if (i & 1) c = -c;
        }
        csh[i] = c;
    }
    __syncthreads();

    // Padded + u-rescaled + MIDPOINT-recentered table. In-range interval k:
    //   P(u) = A + Bu + Cu^2 + Du^3, u in [0,1]
    // Entry j (raw interval it = j-PADL, clamped to k, Delta = it-k + 0.5):
    //   recenter at u0 = Delta+0.5 relative to k's polynomial.
    {
        const float h  = 8.0f / 127.0f;
        const float h2 = h * h;
        const int j  = tid;
        const int it = j - PADL;
        const int k  = min(max(it, 0), 126);
        const float s = (float)(it - k) + 0.5f;    // shift incl. midpoint

        const float A  = ysh[k];
        const float c0 = csh[k];
        const float c1 = csh[k + 1];
        const float B  = (ysh[k + 1] - A) - h2 * (2.0f * c0 + c1) * (1.0f / 3.0f);
        const float C  = c0 * h2;
        const float D  = (c1 - c0) * h2 * (1.0f / 3.0f);

        const float ap = A + s * (B + s * (C + s * D));
        const float bp = B + s * (2.0f * C + 3.0f * D * s);
        const float cp = C + 3.0f * D * s;

        tab[j] = make_float4(ap, bp, cp, D);
    }
    __syncthreads();

    // ---- main evaluation loop ------------------------------------------------
    const float4* p = x4 + (size_t)blockIdx.x * F4_PER_BLOCK + tid;

    float a0 = 0.0f, a1 = 0.0f, a2 = 0.0f, a3 = 0.0f;
#pragma unroll 4
    for (int it = 0; it < F4_PER_BLOCK / NTHREADS; ++it) {
        const float4 v = p[it * NTHREADS];
        eval_lane(v.x, tab, a0);
        eval_lane(v.y, tab, a1);
        eval_lane(v.z, tab, a2);
        eval_lane(v.w, tab, a3);
    }

    float s = (a0 + a1) + (a2 + a3);
#pragma unroll
    for (int o = 16; o > 0; o >>= 1)
        s += __shfl_xor_sync(0xFFFFFFFFu, s, o);

    if ((tid & 31) == 0)
        wsum[tid >> 5] = s;
    __syncthreads();

    if (tid == 0) {
        float t = 0.0f;
#pragma unroll
        for (int w = 0; w < NTHREADS / 32; ++w)
            t += wsum[w];
        g_part[blockIdx.x] = t;
        __threadfence();
        const unsigned int ticket = atomicAdd(&g_ticket, 1u);
        amLast = (ticket == EVAL_BLOCKS - 1);
    }
    __syncthreads();

    // ---- last block: deterministic fixed-order final reduction ---------------
    if (amLast) {
        __threadfence();
        float r = 0.0f;
        // fixed strided order: thread t sums indices t, t+256, t+512, t+768
#pragma unroll
        for (int i = 0; i < EVAL_BLOCKS / NTHREADS; ++i)
            r += g_part[tid + i * NTHREADS];

        __shared__ float sh[NTHREADS];
        sh[tid] = r;
        __syncthreads();
#pragma unroll
        for (int st = NTHREADS / 2; st > 0; st >>= 1) {
            if (tid < st)
                sh[tid] += sh[tid + st];
            __syncthreads();
        }
        if (tid == 0) {
            out[0] = sh[0];
            g_ticket = 0u;   // reset for next call / graph replay
        }
    }
}

// ---------------------------------------------------------------------------
extern "C" void kernel_launch(void* const* d_in, const int* in_sizes, int n_in,
                              void* d_out, int out_size)
{
    const float* x     = (const float*)d_in[0];        // (32,8,256,256) fp32
    const float* nodal = (const float*)d_in[1];        // (8,128) fp32
    float* out = (float*)d_out;

    eval_kernel<<<EVAL_BLOCKS, NTHREADS>>>((const float4*)x, nodal, out);
}

// round 6
// speedup vs baseline: 1.1429x; 1.1429x over previous
#include <cuda_runtime.h>

// NaturalCubicSplinePotential — GB300 sm_103a
//
// R5: conflict-free shared-memory gather via lane-slotted table replication.
// 8 interleaved copies: entry i, slot s at byte offset i*128 + s*16. Slot s
// occupies banks 4s..4s+3 ALWAYS, so with slot = lane&7 each quarter-warp
// LDS.128 phase hits 8 disjoint bank-quads -> 1 wavefront, zero replays,
// independent of the (random) indices. L1 wavefronts per 128 elems: 42 -> 20.
// Smem 32KB/CTA -> 7 CTAs/SM (fits 228KB carveout), grid is still one wave.
//
// Retained from earlier rounds:
//  - closed-form [1,4,1] tridiagonal inverse (lam=2+sqrt(3)), 31-tap conv
//  - padded 256-interval table (no clamp in hot loop)
//  - magic-number floor + midpoint-recentered coefficients (no F2I/I2F)
//  - fused deterministic last-block reduction (ticket + fixed-order sum)

#define NM 8
#define NN 128
#define TABN 256
#define PADL 64
#define NSLOT 8
#define EVAL_BLOCKS 1024
#define F4_PER_BLOCK 4096
#define NTHREADS 256
#define CONV_R 15

__device__ float g_part[EVAL_BLOCKS];
__device__ unsigned int g_ticket;   // zero-init; self-resets each call

#define LOG2_LAM 1.89996863f        // log2(2+sqrt(3))
#define INV_D0   1.07735027f        // 1/(1-lam^-2)
#define MAGIC    12582912.0f        // 1.5 * 2^23
#define MAGIC_I  0x4B400000

// ---------------------------------------------------------------------------
__device__ __forceinline__ void eval_lane(float xv, const float4* __restrict__ tslot,
                                          float& acc)
{
    // t5 = (x+4)*127/8 + 64 - 0.5   (pads folded: 4*15.875 + 63.5 = 127.0)
    const float t5 = __fmaf_rn(xv, 15.875f, 127.0f);
    const float tm = t5 + MAGIC;                    // round(t5) == floor(t) a.e.
    const int   i  = __float_as_int(tm) - MAGIC_I;
    const float v  = t5 - (tm - MAGIC);             // v = u - 0.5 in [-0.5,0.5)
    const float4 cf = tslot[i * NSLOT];             // conflict-free slot gather
    acc += __fmaf_rn(v, __fmaf_rn(v, __fmaf_rn(v, cf.w, cf.z), cf.y), cf.x);
}

__global__ void __launch_bounds__(NTHREADS) eval_kernel(const float4* __restrict__ x4,
                                                        const float* __restrict__ nodal,
                                                        float* __restrict__ out)
{
    __shared__ float4 tab[TABN * NSLOT];                // 32 KB, lane-slotted
    __shared__ float  ysh[NN];
    __shared__ float  pw[256];                          // pw[k] = lam^{-k}
    __shared__ float  srsh[NN + 2 * (CONV_R + 1)];      // padded (-1)^j * r_j
    __shared__ float  csh[NN];
    __shared__ float  wsum[NTHREADS / 32];
    __shared__ bool   amLast;

    const int tid = threadIdx.x;
    // slab (bs,f) = 65536 elems = 4 blocks; marginal index = slab & 7
    const int m = (blockIdx.x >> 2) & 7;

    // ---- prologue: closed-form spline solve --------------------------------
    if (tid < NN)
        ysh[tid] = nodal[m * NN + tid];
    pw[tid] = exp2f(-LOG2_LAM * (float)tid);
    if (tid < NN + 2 * (CONV_R + 1))
        srsh[tid] = 0.0f;
    __syncthreads();

    const float inv_h2 = (127.0f / 8.0f) * (127.0f / 8.0f);
    if (tid >= 1 && tid <= 126) {
        float r = 3.0f * (ysh[tid - 1] - 2.0f * ysh[tid] + ysh[tid + 1]) * inv_h2;
        srsh[(CONV_R + 1) + tid] = (tid & 1) ? -r : r;
    }
    __syncthreads();

    if (tid < NN) {
        const int i = tid;
        float c = 0.0f;
        if (i >= 1 && i <= 126) {
#pragma unroll
            for (int dj = -CONV_R; dj <= CONV_R; ++dj) {
                const int j  = i + dj;
                const int jc = min(max(j, 1), 126);
                const int mi = min(i, jc);
                const int mx = max(i, jc);
                const float w = pw[(dj < 0 ? -dj : dj) + 1]
                              * (1.0f - pw[2 * mi])
                              * (1.0f - pw[2 * (127 - mx)]);
                c = __fmaf_rn(w, srsh[(CONV_R + 1) + j], c);
            }
            c *= INV_D0;
            if (i & 1) c = -c;
        }
        csh[i] = c;
    }
    __syncthreads();

    // ---- padded + midpoint-recentered table, replicated into 8 slots -------
    {
        const float h  = 8.0f / 127.0f;
        const float h2 = h * h;
        const int j  = tid;
        const int it = j - PADL;
        const int k  = min(max(it, 0), 126);
        const float s = (float)(it - k) + 0.5f;     // shift incl. midpoint

        const float A  = ysh[k];
        const float c0 = csh[k];
        const float c1 = csh[k + 1];
        const float B  = (ysh[k + 1] - A) - h2 * (2.0f * c0 + c1) * (1.0f / 3.0f);
        const float C  = c0 * h2;
        const float D  = (c1 - c0) * h2 * (1.0f / 3.0f);

        const float4 cf = make_float4(A + s * (B + s * (C + s * D)),
                                      B + s * (2.0f * C + 3.0f * D * s),
                                      C + 3.0f * D * s,
                                      D);
#pragma unroll
        for (int sl = 0; sl < NSLOT; ++sl)
            tab[j * NSLOT + sl] = cf;
    }
    __syncthreads();

    // ---- main evaluation loop ----------------------------------------------
    const float4* tslot = tab + (tid & 7);          // this lane's bank-quad
    const float4* p = x4 + (size_t)blockIdx.x * F4_PER_BLOCK + tid;

    float a0 = 0.0f, a1 = 0.0f, a2 = 0.0f, a3 = 0.0f;
#pragma unroll 4
    for (int it = 0; it < F4_PER_BLOCK / NTHREADS; ++it) {
        const float4 v = p[it * NTHREADS];
        eval_lane(v.x, tslot, a0);
        eval_lane(v.y, tslot, a1);
        eval_lane(v.z, tslot, a2);
        eval_lane(v.w, tslot, a3);
    }

    float s = (a0 + a1) + (a2 + a3);
#pragma unroll
    for (int o = 16; o > 0; o >>= 1)
        s += __shfl_xor_sync(0xFFFFFFFFu, s, o);

    if ((tid & 31) == 0)
        wsum[tid >> 5] = s;
    __syncthreads();

    if (tid == 0) {
        float t = 0.0f;
#pragma unroll
        for (int w = 0; w < NTHREADS / 32; ++w)
            t += wsum[w];
        g_part[blockIdx.x] = t;
        __threadfence();
        const unsigned int ticket = atomicAdd(&g_ticket, 1u);
        amLast = (ticket == EVAL_BLOCKS - 1);
    }
    __syncthreads();

    // ---- last block: deterministic fixed-order final reduction -------------
    if (amLast) {
        __threadfence();
        float r = 0.0f;
#pragma unroll
        for (int i = 0; i < EVAL_BLOCKS / NTHREADS; ++i)
            r += g_part[tid + i * NTHREADS];

        __shared__ float sh[NTHREADS];
        sh[tid] = r;
        __syncthreads();
#pragma unroll
        for (int st = NTHREADS / 2; st > 0; st >>= 1) {
            if (tid < st)
                sh[tid] += sh[tid + st];
            __syncthreads();
        }
        if (tid == 0) {
            out[0] = sh[0];
            g_ticket = 0u;   // reset for next call / graph replay
        }
    }
}

// ---------------------------------------------------------------------------
extern "C" void kernel_launch(void* const* d_in, const int* in_sizes, int n_in,
                              void* d_out, int out_size)
{
    const float* x     = (const float*)d_in[0];        // (32,8,256,256) fp32
    const float* nodal = (const float*)d_in[1];        // (8,128) fp32
    float* out = (float*)d_out;

    eval_kernel<<<EVAL_BLOCKS, NTHREADS>>>((const float4*)x, nodal, out);
}